// round 14
// baseline (speedup 1.0000x reference)
#include <cuda_runtime.h>
#include <cuda_fp16.h>
#include <cstdint>

// ===========================================================================
// CharLSTMEmbedding: B=32, T=128, L=16, VOCAB=256, E=256, H=512
// sm_103 plain target -> mma.sync HMMA + cp.async.bulk loads.
//
// R14 == R13 resubmit (R13 bench was an infra failure, kernel never ran):
//  * 3-term hi/lo fp16 GEMM with MIXED accumulators:
//      term1 Ahi*Bhi  -> f32 accumulate (rt 8)
//      terms Ahi*Blo + Alo*Bhi -> ONE shared fp16 accumulator (rt 4)
//    -> tensor issue cycles per chunk: 768 -> 512 (-33%); correction sums are
//    ~2^-11 of gates so fp16 accumulation adds only ~2e-7 abs error.
//  * everything else as R10: sorted active prefix + early exit, bulk-copy
//    3-stage pipeline, full/empty mbars, fused LSTM epilogue, per-step launch.
// ===========================================================================

#define BT   4096
#define SL   16
#define HD   512
#define ED   256
#define NV   256
#define G4   2048

#define TIL  8192              // one 128x32-half tile (hi or lo)
#define CK2  16384             // hi+lo pair
#define NCK  16                // K chunks of 32

__device__ __align__(1024) unsigned char g_W[16 * NCK * CK2];     // 4 MB
__device__ __align__(1024) unsigned char g_A[2][32 * NCK * CK2];  // 2 x 8 MB
__device__ __align__(256) float g_tbl[NV * G4];                   // 2 MB
__device__ __align__(256) float g_C[BT * HD];                     // 8 MB
__device__ int g_perm[BT];      // sorted-pos -> original row
__device__ int g_lens_s[BT];    // lens in sorted order (descending)
__device__ int g_Mt[SL];        // M_t = #(lens > t)

// ------------------------------ helpers -----------------------------------

__device__ __forceinline__ uint32_t smem_u32(const void* p) {
    uint32_t a;
    asm("{ .reg .u64 t; cvta.to.shared.u64 t, %1; cvt.u32.u64 %0, t; }"
        : "=r"(a) : "l"(p));
    return a;
}

// paired-row swizzle for 128row x 64B tiles
__device__ __forceinline__ uint32_t swz32(uint32_t r, uint32_t x) {
    return (r >> 1) * 128u + ((((r & 1u) << 6) + x) ^ ((r & 14u) << 3));
}

__device__ __forceinline__ void bulk_cp(uint32_t dst, const void* src,
                                        uint32_t bytes, uint32_t mbar) {
    asm volatile(
        "cp.async.bulk.shared::cluster.global.mbarrier::complete_tx::bytes "
        "[%0], [%1], %2, [%3];"
        :: "r"(dst), "l"(src), "r"(bytes), "r"(mbar) : "memory");
}

__device__ __forceinline__ void mbar_init(uint32_t mbar, uint32_t cnt) {
    asm volatile("mbarrier.init.shared.b64 [%0], %1;" :: "r"(mbar), "r"(cnt)
                 : "memory");
}
__device__ __forceinline__ void mbar_expect(uint32_t mbar, uint32_t bytes) {
    asm volatile("mbarrier.arrive.expect_tx.shared.b64 _, [%0], %1;"
                 :: "r"(mbar), "r"(bytes) : "memory");
}
__device__ __forceinline__ void mbar_arrive(uint32_t mbar) {
    asm volatile("mbarrier.arrive.shared.b64 _, [%0];" :: "r"(mbar) : "memory");
}
__device__ __forceinline__ void mbar_wait(uint32_t mbar, uint32_t parity) {
    asm volatile(
        "{\n\t.reg .pred P;\n\t"
        "WL_%=:\n\t"
        "mbarrier.try_wait.parity.acquire.cta.shared::cta.b64 P, [%0], %1, 0x989680;\n\t"
        "@P bra.uni WD_%=;\n\t"
        "bra.uni WL_%=;\n\t"
        "WD_%=:\n\t}"
        :: "r"(mbar), "r"(parity) : "memory");
}

__device__ __forceinline__ void ldsm4(uint32_t* r, uint32_t addr) {
    asm volatile("ldmatrix.sync.aligned.m8n8.x4.shared.b16 {%0,%1,%2,%3}, [%4];"
                 : "=r"(r[0]), "=r"(r[1]), "=r"(r[2]), "=r"(r[3]) : "r"(addr));
}
__device__ __forceinline__ void ldsm2(uint32_t* r, uint32_t addr) {
    asm volatile("ldmatrix.sync.aligned.m8n8.x2.shared.b16 {%0,%1}, [%2];"
                 : "=r"(r[0]), "=r"(r[1]) : "r"(addr));
}

// f32-accumulate HMMA (rt 8)
__device__ __forceinline__ void mma_f32(float* d, const uint32_t* a,
                                        const uint32_t* b) {
    asm volatile(
        "mma.sync.aligned.m16n8k16.row.col.f32.f16.f16.f32 "
        "{%0,%1,%2,%3}, {%4,%5,%6,%7}, {%8,%9}, {%0,%1,%2,%3};"
        : "+f"(d[0]), "+f"(d[1]), "+f"(d[2]), "+f"(d[3])
        : "r"(a[0]), "r"(a[1]), "r"(a[2]), "r"(a[3]), "r"(b[0]), "r"(b[1]));
}
// f16-accumulate HMMA (rt 4) for the small correction terms
__device__ __forceinline__ void mma_f16(uint32_t* d, const uint32_t* a,
                                        const uint32_t* b) {
    asm volatile(
        "mma.sync.aligned.m16n8k16.row.col.f16.f16.f16.f16 "
        "{%0,%1}, {%2,%3,%4,%5}, {%6,%7}, {%0,%1};"
        : "+r"(d[0]), "+r"(d[1])
        : "r"(a[0]), "r"(a[1]), "r"(a[2]), "r"(a[3]), "r"(b[0]), "r"(b[1]));
}

__device__ __forceinline__ float sigf(float x) {
    return __fdividef(1.0f, 1.0f + __expf(-x));
}
__device__ __forceinline__ float tanhfast(float x) {
    return __fdividef(2.0f, 1.0f + __expf(-2.0f * x)) - 1.0f;
}

// ------------------------------ prep kernels ------------------------------

// counting sort by length, descending; deterministic within-bin order.
__global__ void prep_perm(const int* __restrict__ lens) {
    __shared__ int cnt[17], off[17];
    int tid = threadIdx.x;
    if (tid < 17) cnt[tid] = 0;
    __syncthreads();
    for (int i = tid; i < BT; i += 512) atomicAdd(&cnt[lens[i]], 1);
    __syncthreads();
    if (tid == 0) {
        int acc = 0;
        for (int l = 16; l >= 1; l--) { off[l] = acc; acc += cnt[l]; }
        g_Mt[0] = BT;
        for (int t = 1; t < SL; t++) g_Mt[t] = off[t];   // #(lens > t)
    }
    __syncthreads();
    int w = tid >> 5, lane = tid & 31;
    int l = w + 1;                                   // bins 1..16
    int p = off[l];
    for (int base = 0; base < BT; base += 32) {
        int i = base + lane;
        bool m = (lens[i] == l);
        unsigned msk = __ballot_sync(0xffffffffu, m);
        if (m) {
            int rank = __popc(msk & ((1u << lane) - 1));
            g_perm[p + rank] = i;
            g_lens_s[p + rank] = l;
        }
        p += __popc(msk);
    }
}

__global__ void prep_w(const float* __restrict__ W) {
    int idx = blockIdx.x * 256 + threadIdx.x;      // < G4*HD
    int np = idx >> 9, k = idx & 511;
    int hc = ((np >> 5) << 3) + (np & 7);
    int g  = (np >> 3) & 3;
    float v = W[(g * HD + hc) * HD + k];
    __half hi = __float2half_rn(v);
    __half lo = __float2half_rn(v - __half2float(hi));
    uint32_t base = (uint32_t)((np >> 7) * NCK + (k >> 5)) * CK2;
    uint32_t off  = swz32((uint32_t)(np & 127), (uint32_t)((k & 31) * 2));
    *(__half*)(g_W + base + off)       = hi;
    *(__half*)(g_W + base + TIL + off) = lo;
}

__global__ void prep_tbl(const float* __restrict__ emb,
                         const float* __restrict__ Wih,
                         const float* __restrict__ bi,
                         const float* __restrict__ bh) {
    __shared__ __align__(16) float e[ED];
    int v = blockIdx.y;
    for (int i = threadIdx.x; i < ED; i += blockDim.x)
        e[i] = emb[v * ED + i];
    __syncthreads();

    int np = blockIdx.x * 128 + threadIdx.x;
    int hc = ((np >> 5) << 3) + (np & 7);
    int g  = (np >> 3) & 3;
    int n  = g * HD + hc;
    const float4* w4 = (const float4*)(Wih + n * ED);
    const float4* e4 = (const float4*)e;
    float s = bi[n] + bh[n];
#pragma unroll 8
    for (int k = 0; k < ED / 4; k++) {
        float4 wv = w4[k];
        float4 ev = e4[k];
        s += ev.x * wv.x + ev.y * wv.y + ev.z * wv.z + ev.w * wv.w;
    }
    g_tbl[v * G4 + np] = s;
}

// step 0 in sorted row space; rows with lens==1 freeze here -> write out
__global__ void step0(const int* __restrict__ seq, float* __restrict__ out) {
    int ms = blockIdx.x;                       // sorted row
    int hc = blockIdx.y * 128 + threadIdx.x;
    int orig = g_perm[ms];
    int id = seq[orig * SL];
    int base = ((hc >> 3) << 5) + (hc & 7);    // gate stride 8 in tbl
    const float* tr = g_tbl + id * G4;
    float cn = sigf(tr[base]) * tanhfast(tr[base + 16]);
    float hn = sigf(tr[base + 24]) * tanhfast(cn);
    __half hi = __float2half_rn(hn);
    __half lo = __float2half_rn(hn - __half2float(hi));
    uint32_t tb  = (uint32_t)((ms >> 7) * NCK + (hc >> 5)) * CK2;
    uint32_t off = swz32((uint32_t)(ms & 127), (uint32_t)((hc & 31) * 2));
    *(__half*)(g_A[0] + tb + off)       = hi;
    *(__half*)(g_A[0] + tb + TIL + off) = lo;
    g_C[ms * HD + hc] = cn;
    if (g_lens_s[ms] == 1) out[orig * HD + hc] = hn;
}

// --------------------------- recurrent step -------------------------------
// CTA 128(m) x 128(n'), 256 threads, 8 warps (2m x 4n), warp 64x32.
// 16 K-chunks of 32; 3-stage pipeline with full (tx) + empty (count 8) mbars.

#define SMEM_TOTAL (1024 + 3 * 32768)

__global__ void __launch_bounds__(256, 2)
lstm_step(const int* __restrict__ seq, float* __restrict__ out_f, int t) {
    // active-prefix early exit
    const int m0 = (int)blockIdx.y * 128;
    const int Mpad = (g_Mt[t] + 127) & ~127;
    if (m0 >= Mpad) return;

    extern __shared__ char smem[];
    const uint32_t sb = smem_u32(smem);
    const int tid = threadIdx.x, lid = tid & 31;
    const int wm = (tid >> 5) >> 2;            // 0..1
    const int wn = (tid >> 5) & 3;             // 0..3

    const unsigned char* __restrict__ Asrc =
        g_A[(t + 1) & 1] + (size_t)blockIdx.y * NCK * CK2;
    const unsigned char* __restrict__ Wsrc =
        g_W + (size_t)blockIdx.x * NCK * CK2;

    // mbars: full[b] @ sb+b*8 (count1, tx), empty[b] @ sb+24+b*8 (count 8)
    if (tid == 0) {
#pragma unroll
        for (int b = 0; b < 3; b++) {
            mbar_init(sb + b * 8, 1);
            mbar_init(sb + 24 + b * 8, 8);
        }
    }
    __syncthreads();

    auto issue = [&](int ck) {
        uint32_t buf = (uint32_t)(ck % 3);
        uint32_t dst = sb + 1024 + buf * 32768;
        uint32_t mb  = sb + buf * 8;
        mbar_expect(mb, 32768);
        bulk_cp(dst,       Asrc + ck * CK2, CK2, mb);   // Ahi|Alo
        bulk_cp(dst + CK2, Wsrc + ck * CK2, CK2, mb);   // Bhi|Blo
    };
    if (tid == 0) { issue(0); issue(1); issue(2); }

    float    acc [4][4][4];          // main term, f32 accumulate
    uint32_t acc2[4][4][2];          // corrections, f16 accumulate (half2 x2)
#pragma unroll
    for (int a = 0; a < 4; a++)
#pragma unroll
        for (int b = 0; b < 4; b++) {
#pragma unroll
            for (int c = 0; c < 4; c++) acc[a][b][c] = 0.0f;
            acc2[a][b][0] = 0u; acc2[a][b][1] = 0u;
        }

    const uint32_t arow = (uint32_t)(wm * 64 + (lid & 15));
    const uint32_t acs  = (uint32_t)((lid >> 4) * 16);        // A k-seg
    const uint32_t brow = (uint32_t)(wn * 32 + (lid & 7));
    const uint32_t bcs  = (uint32_t)(((lid >> 3) & 1) * 16);  // B k-seg

    for (int ck = 0; ck < NCK; ck++) {
        const uint32_t buf = (uint32_t)(ck % 3);
        const uint32_t par = (uint32_t)((ck / 3) & 1);
        mbar_wait(sb + buf * 8, par);                 // full

        const uint32_t cb = sb + 1024 + buf * 32768;
        const uint32_t sAhi = cb, sAlo = cb + TIL;
        const uint32_t sBhi = cb + 2 * TIL, sBlo = cb + 3 * TIL;

#pragma unroll
        for (int k16 = 0; k16 < 2; k16++) {
            const uint32_t ax = (uint32_t)(k16 * 32) + acs;
            const uint32_t bx = (uint32_t)(k16 * 32) + bcs;
            uint32_t bhf[4][2], blf[4][2];
#pragma unroll
            for (int g = 0; g < 4; g++) {
                uint32_t ro = swz32(brow + (uint32_t)(g * 8), bx);
                ldsm2(bhf[g], sBhi + ro);
                ldsm2(blf[g], sBlo + ro);
            }
#pragma unroll
            for (int mt = 0; mt < 4; mt++) {
                uint32_t ro = swz32(arow + (uint32_t)(mt * 16), ax);
                uint32_t ah[4], al[4];
                ldsm4(ah, sAhi + ro);
                ldsm4(al, sAlo + ro);
                // main term: f32 accumulate (rt 8)
#pragma unroll
                for (int g = 0; g < 4; g++) mma_f32(acc[mt][g], ah, bhf[g]);
                // corrections: shared f16 accumulator (rt 4); same-acc RAW
                // distance = 4 instructions
#pragma unroll
                for (int g = 0; g < 4; g++) mma_f16(acc2[mt][g], ah, blf[g]);
#pragma unroll
                for (int g = 0; g < 4; g++) mma_f16(acc2[mt][g], al, bhf[g]);
            }
        }
        if (lid == 0) mbar_arrive(sb + 24 + buf * 8);  // this warp done
        if (tid == 0 && ck + 3 < NCK) {
            mbar_wait(sb + 24 + buf * 8, par);         // all 8 warps done
            issue(ck + 3);
        }
    }

    // ---------------- fused LSTM epilogue ----------------
    const int q = lid & 3, r = lid >> 2;
    const int n0 = blockIdx.x * 128;
    const int cn0 = n0 + wn * 32;
    const int hcb = (cn0 >> 2) + 2 * q;            // even, pair (hcb, hcb+1)
    unsigned char* __restrict__ Aout = g_A[t & 1];
    const unsigned char* __restrict__ Ain = g_A[(t + 1) & 1];

    const uint32_t ckh  = (uint32_t)(hcb >> 5);
    const uint32_t xoff = (uint32_t)((hcb & 31) * 2);

#pragma unroll
    for (int mt = 0; mt < 4; mt++) {
#pragma unroll
        for (int v = 0; v < 2; v++) {
            const int ms = m0 + wm * 64 + mt * 16 + r + v * 8;   // sorted row
            const int L  = g_lens_s[ms];
            const bool act = L > t;
            const uint32_t tb  = ((uint32_t)(ms >> 7) * NCK + ckh) * CK2;
            const uint32_t off = swz32((uint32_t)(ms & 127), xoff);
            __half2* phiO = (__half2*)(Aout + tb + off);
            __half2* ploO = (__half2*)(Aout + tb + TIL + off);
            if (act) {
                const int orig = g_perm[ms];
                const int id = seq[orig * SL + t];
                const float* tr = g_tbl + id * G4 + cn0 + 2 * q;
                float2 cp = *(const float2*)(g_C + ms * HD + hcb);
                float co[2] = {cp.x, cp.y};
                // correction sums for this (mt, v): one half2 per gate
                float2 cr[4];
#pragma unroll
                for (int g = 0; g < 4; g++)
                    cr[g] = __half22float2(
                        *(const __half2*)&acc2[mt][g][v]);
                float h2[2], c2[2];
#pragma unroll
                for (int j = 0; j < 2; j++) {
                    float pi = acc[mt][0][2 * v + j] +
                               (j ? cr[0].y : cr[0].x) + tr[0 + j];
                    float pf = acc[mt][1][2 * v + j] +
                               (j ? cr[1].y : cr[1].x) + tr[8 + j];
                    float pg = acc[mt][2][2 * v + j] +
                               (j ? cr[2].y : cr[2].x) + tr[16 + j];
                    float po = acc[mt][3][2 * v + j] +
                               (j ? cr[3].y : cr[3].x) + tr[24 + j];
                    float ig = sigf(pi), fg = sigf(pf);
                    float gg = tanhfast(pg), og = sigf(po);
                    float cc = fg * co[j] + ig * gg;
                    c2[j] = cc;
                    h2[j] = og * tanhfast(cc);
                }
                *(float2*)(g_C + ms * HD + hcb) = make_float2(c2[0], c2[1]);
                __half hi0 = __float2half_rn(h2[0]);
                __half hi1 = __float2half_rn(h2[1]);
                __half lo0 = __float2half_rn(h2[0] - __half2float(hi0));
                __half lo1 = __float2half_rn(h2[1] - __half2float(hi1));
                *phiO = __halves2half2(hi0, hi1);
                *ploO = __halves2half2(lo0, lo1);
                if (L == t + 1)                        // freezes after this
                    *(float2*)(out_f + orig * HD + hcb) =
                        make_float2(h2[0], h2[1]);
            } else {
                // frozen boundary-tile row: forward state for ping-pong
                *phiO = *(const __half2*)(Ain + tb + off);
                *ploO = *(const __half2*)(Ain + tb + TIL + off);
            }
        }
    }
}

// ------------------------------ host entry --------------------------------
// Inputs: char_seq_padded(i32), char_lengths(i32), emb, W_ih, W_hh, b_ih, b_hh
extern "C" void kernel_launch(void* const* d_in, const int* in_sizes, int n_in,
                              void* d_out, int out_size) {
    const int*   seq  = (const int*)  d_in[0];
    const int*   lens = (const int*)  d_in[1];
    const float* emb  = (const float*)d_in[2];
    const float* W_ih = (const float*)d_in[3];
    const float* W_hh = (const float*)d_in[4];
    const float* b_ih = (const float*)d_in[5];
    const float* b_hh = (const float*)d_in[6];
    float* out = (float*)d_out;

    cudaFuncSetAttribute(lstm_step,
                         cudaFuncAttributeMaxDynamicSharedMemorySize,
                         SMEM_TOTAL);

    prep_perm<<<1, 512>>>(lens);
    prep_w<<<(G4 * HD) / 256, 256>>>(W_hh);
    prep_tbl<<<dim3(G4 / 128, NV), 128>>>(emb, W_ih, b_ih, b_hh);
    step0<<<dim3(BT, HD / 128), 128>>>(seq, out);

    for (int t = 1; t < SL; t++)
        lstm_step<<<dim3(G4 / 128, BT / 128), 256, SMEM_TOTAL>>>(seq, out, t);
}

// round 15
// speedup vs baseline: 1.2204x; 1.2204x over previous
#include <cuda_runtime.h>
#include <cuda_fp16.h>
#include <cstdint>

// ===========================================================================
// CharLSTMEmbedding: B=32, T=128, L=16, VOCAB=256, E=256, H=512
// sm_103 plain target -> mma.sync HMMA + cp.async.bulk loads.
//
// R15 (fixes R14's register-spill failure, keeps its mixed-precision math):
//  * 512-thread CTA, 16 warps (4m x 4n), warp tile 32x32, ONE CTA per SM
//    -> 32 f32 + 16 f16 accs/thread (~100 regs, no spills at 128-reg budget)
//  * mixed accumulators: Ahi*Bhi -> f32 (rt 8); Ahi*Blo + Alo*Bhi -> shared
//    f16 acc (rt 4)  => issue floor 1536 -> 1024 cyc/SMSP/chunk (x0.67)
//  * 5-stage bulk-copy pipeline (161KB smem) + grid-stride tile loop with a
//    CONTINUOUS cross-tile chunk pipeline (no per-tile prologue bubbles) and
//    better wave quantization (grid = #SMs)
//  * unchanged: sorted active prefix, tile layouts, fused epilogue, per-step
//    launches, step0/prep kernels.
// ===========================================================================

#define BT   4096
#define SL   16
#define HD   512
#define ED   256
#define NV   256
#define G4   2048

#define TIL  8192              // one 128x32-half tile (hi or lo)
#define CK2  16384             // hi+lo pair
#define NCK  16                // K chunks of 32
#define NSTG 5                 // pipeline stages

__device__ __align__(1024) unsigned char g_W[16 * NCK * CK2];     // 4 MB
__device__ __align__(1024) unsigned char g_A[2][32 * NCK * CK2];  // 2 x 8 MB
__device__ __align__(256) float g_tbl[NV * G4];                   // 2 MB
__device__ __align__(256) float g_C[BT * HD];                     // 8 MB
__device__ int g_perm[BT];      // sorted-pos -> original row
__device__ int g_lens_s[BT];    // lens in sorted order (descending)
__device__ int g_Mt[SL];        // M_t = #(lens > t)

// ------------------------------ helpers -----------------------------------

__device__ __forceinline__ uint32_t smem_u32(const void* p) {
    uint32_t a;
    asm("{ .reg .u64 t; cvta.to.shared.u64 t, %1; cvt.u32.u64 %0, t; }"
        : "=r"(a) : "l"(p));
    return a;
}

// paired-row swizzle for 128row x 64B tiles
__device__ __forceinline__ uint32_t swz32(uint32_t r, uint32_t x) {
    return (r >> 1) * 128u + ((((r & 1u) << 6) + x) ^ ((r & 14u) << 3));
}

__device__ __forceinline__ void bulk_cp(uint32_t dst, const void* src,
                                        uint32_t bytes, uint32_t mbar) {
    asm volatile(
        "cp.async.bulk.shared::cluster.global.mbarrier::complete_tx::bytes "
        "[%0], [%1], %2, [%3];"
        :: "r"(dst), "l"(src), "r"(bytes), "r"(mbar) : "memory");
}

__device__ __forceinline__ void mbar_init(uint32_t mbar, uint32_t cnt) {
    asm volatile("mbarrier.init.shared.b64 [%0], %1;" :: "r"(mbar), "r"(cnt)
                 : "memory");
}
__device__ __forceinline__ void mbar_expect(uint32_t mbar, uint32_t bytes) {
    asm volatile("mbarrier.arrive.expect_tx.shared.b64 _, [%0], %1;"
                 :: "r"(mbar), "r"(bytes) : "memory");
}
__device__ __forceinline__ void mbar_arrive(uint32_t mbar) {
    asm volatile("mbarrier.arrive.shared.b64 _, [%0];" :: "r"(mbar) : "memory");
}
__device__ __forceinline__ void mbar_wait(uint32_t mbar, uint32_t parity) {
    asm volatile(
        "{\n\t.reg .pred P;\n\t"
        "WL_%=:\n\t"
        "mbarrier.try_wait.parity.acquire.cta.shared::cta.b64 P, [%0], %1, 0x989680;\n\t"
        "@P bra.uni WD_%=;\n\t"
        "bra.uni WL_%=;\n\t"
        "WD_%=:\n\t}"
        :: "r"(mbar), "r"(parity) : "memory");
}

__device__ __forceinline__ void ldsm4(uint32_t* r, uint32_t addr) {
    asm volatile("ldmatrix.sync.aligned.m8n8.x4.shared.b16 {%0,%1,%2,%3}, [%4];"
                 : "=r"(r[0]), "=r"(r[1]), "=r"(r[2]), "=r"(r[3]) : "r"(addr));
}
__device__ __forceinline__ void ldsm2(uint32_t* r, uint32_t addr) {
    asm volatile("ldmatrix.sync.aligned.m8n8.x2.shared.b16 {%0,%1}, [%2];"
                 : "=r"(r[0]), "=r"(r[1]) : "r"(addr));
}

// f32-accumulate HMMA (rt 8)
__device__ __forceinline__ void mma_f32(float* d, const uint32_t* a,
                                        const uint32_t* b) {
    asm volatile(
        "mma.sync.aligned.m16n8k16.row.col.f32.f16.f16.f32 "
        "{%0,%1,%2,%3}, {%4,%5,%6,%7}, {%8,%9}, {%0,%1,%2,%3};"
        : "+f"(d[0]), "+f"(d[1]), "+f"(d[2]), "+f"(d[3])
        : "r"(a[0]), "r"(a[1]), "r"(a[2]), "r"(a[3]), "r"(b[0]), "r"(b[1]));
}
// f16-accumulate HMMA (rt 4) for the small correction terms
__device__ __forceinline__ void mma_f16(uint32_t* d, const uint32_t* a,
                                        const uint32_t* b) {
    asm volatile(
        "mma.sync.aligned.m16n8k16.row.col.f16.f16.f16.f16 "
        "{%0,%1}, {%2,%3,%4,%5}, {%6,%7}, {%0,%1};"
        : "+r"(d[0]), "+r"(d[1])
        : "r"(a[0]), "r"(a[1]), "r"(a[2]), "r"(a[3]), "r"(b[0]), "r"(b[1]));
}

__device__ __forceinline__ float sigf(float x) {
    return __fdividef(1.0f, 1.0f + __expf(-x));
}
__device__ __forceinline__ float tanhfast(float x) {
    return __fdividef(2.0f, 1.0f + __expf(-2.0f * x)) - 1.0f;
}

// ------------------------------ prep kernels ------------------------------

// counting sort by length, descending; deterministic within-bin order.
__global__ void prep_perm(const int* __restrict__ lens) {
    __shared__ int cnt[17], off[17];
    int tid = threadIdx.x;
    if (tid < 17) cnt[tid] = 0;
    __syncthreads();
    for (int i = tid; i < BT; i += 512) atomicAdd(&cnt[lens[i]], 1);
    __syncthreads();
    if (tid == 0) {
        int acc = 0;
        for (int l = 16; l >= 1; l--) { off[l] = acc; acc += cnt[l]; }
        g_Mt[0] = BT;
        for (int t = 1; t < SL; t++) g_Mt[t] = off[t];   // #(lens > t)
    }
    __syncthreads();
    int w = tid >> 5, lane = tid & 31;
    int l = w + 1;                                   // bins 1..16
    int p = off[l];
    for (int base = 0; base < BT; base += 32) {
        int i = base + lane;
        bool m = (lens[i] == l);
        unsigned msk = __ballot_sync(0xffffffffu, m);
        if (m) {
            int rank = __popc(msk & ((1u << lane) - 1));
            g_perm[p + rank] = i;
            g_lens_s[p + rank] = l;
        }
        p += __popc(msk);
    }
}

__global__ void prep_w(const float* __restrict__ W) {
    int idx = blockIdx.x * 256 + threadIdx.x;      // < G4*HD
    int np = idx >> 9, k = idx & 511;
    int hc = ((np >> 5) << 3) + (np & 7);
    int g  = (np >> 3) & 3;
    float v = W[(g * HD + hc) * HD + k];
    __half hi = __float2half_rn(v);
    __half lo = __float2half_rn(v - __half2float(hi));
    uint32_t base = (uint32_t)((np >> 7) * NCK + (k >> 5)) * CK2;
    uint32_t off  = swz32((uint32_t)(np & 127), (uint32_t)((k & 31) * 2));
    *(__half*)(g_W + base + off)       = hi;
    *(__half*)(g_W + base + TIL + off) = lo;
}

__global__ void prep_tbl(const float* __restrict__ emb,
                         const float* __restrict__ Wih,
                         const float* __restrict__ bi,
                         const float* __restrict__ bh) {
    __shared__ __align__(16) float e[ED];
    int v = blockIdx.y;
    for (int i = threadIdx.x; i < ED; i += blockDim.x)
        e[i] = emb[v * ED + i];
    __syncthreads();

    int np = blockIdx.x * 128 + threadIdx.x;
    int hc = ((np >> 5) << 3) + (np & 7);
    int g  = (np >> 3) & 3;
    int n  = g * HD + hc;
    const float4* w4 = (const float4*)(Wih + n * ED);
    const float4* e4 = (const float4*)e;
    float s = bi[n] + bh[n];
#pragma unroll 8
    for (int k = 0; k < ED / 4; k++) {
        float4 wv = w4[k];
        float4 ev = e4[k];
        s += ev.x * wv.x + ev.y * wv.y + ev.z * wv.z + ev.w * wv.w;
    }
    g_tbl[v * G4 + np] = s;
}

// step 0 in sorted row space; rows with lens==1 freeze here -> write out
__global__ void step0(const int* __restrict__ seq, float* __restrict__ out) {
    int ms = blockIdx.x;                       // sorted row
    int hc = blockIdx.y * 128 + threadIdx.x;
    int orig = g_perm[ms];
    int id = seq[orig * SL];
    int base = ((hc >> 3) << 5) + (hc & 7);    // gate stride 8 in tbl
    const float* tr = g_tbl + id * G4;
    float cn = sigf(tr[base]) * tanhfast(tr[base + 16]);
    float hn = sigf(tr[base + 24]) * tanhfast(cn);
    __half hi = __float2half_rn(hn);
    __half lo = __float2half_rn(hn - __half2float(hi));
    uint32_t tb  = (uint32_t)((ms >> 7) * NCK + (hc >> 5)) * CK2;
    uint32_t off = swz32((uint32_t)(ms & 127), (uint32_t)((hc & 31) * 2));
    *(__half*)(g_A[0] + tb + off)       = hi;
    *(__half*)(g_A[0] + tb + TIL + off) = lo;
    g_C[ms * HD + hc] = cn;
    if (g_lens_s[ms] == 1) out[orig * HD + hc] = hn;
}

// --------------------------- recurrent step -------------------------------
// grid = #SMs, 512 threads, 16 warps (4m x 4n), warp 32x32, 1 CTA/SM.
// Grid-stride over 128x128 tiles; continuous 5-stage chunk pipeline across
// tile boundaries. full (tx) + empty (count 16) mbars.

#define SMEM_TOTAL (1024 + NSTG * 32768)

__global__ void __launch_bounds__(512, 1)
lstm_step(const int* __restrict__ seq, float* __restrict__ out_f, int t) {
    const int Mpad = (g_Mt[t] + 127) & ~127;
    const int ntiles = (Mpad >> 7) * 16;
    const int o = (int)blockIdx.x;
    const int grid = (int)gridDim.x;
    const int mytiles = (o < ntiles) ? ((ntiles - 1 - o) / grid + 1) : 0;
    const int n_me = mytiles << 4;
    if (n_me == 0) return;

    extern __shared__ char smem[];
    const uint32_t sb = smem_u32(smem);
    const int tid = threadIdx.x, lid = tid & 31;
    const int wm = (tid >> 5) >> 2;            // 0..3 (m group)
    const int wn = (tid >> 5) & 3;             // 0..3 (n group)

    const unsigned char* __restrict__ Abase = g_A[(t + 1) & 1];
    unsigned char* __restrict__ Aout = g_A[t & 1];
    const unsigned char* __restrict__ Ain = Abase;

    // mbars: full[b] @ sb+b*8 (count1, tx), empty[b] @ sb+64+b*8 (count 16)
    if (tid == 0) {
#pragma unroll
        for (int b = 0; b < NSTG; b++) {
            mbar_init(sb + b * 8, 1);
            mbar_init(sb + 64 + b * 8, 16);
        }
    }
    __syncthreads();

    auto issue_chunk = [&](int j) {
        const int tile = o + (j >> 4) * grid;
        const int mx = tile >> 4, nx = tile & 15, ck = j & 15;
        const int u = j / NSTG;
        const uint32_t buf = (uint32_t)(j % NSTG);
        if (u > 0) mbar_wait(sb + 64 + buf * 8, (uint32_t)((u - 1) & 1));
        const uint32_t dst = sb + 1024 + buf * 32768;
        const uint32_t mb  = sb + buf * 8;
        mbar_expect(mb, 32768);
        bulk_cp(dst,       Abase + ((size_t)mx * NCK + ck) * CK2, CK2, mb);
        bulk_cp(dst + CK2, g_W   + ((size_t)nx * NCK + ck) * CK2, CK2, mb);
    };
    if (tid == 0) {
        const int pre = n_me < NSTG ? n_me : NSTG;
        for (int jj = 0; jj < pre; jj++) issue_chunk(jj);
    }

    float    acc [2][4][4];          // main term, f32 accumulate
    uint32_t acc2[2][4][2];          // corrections, f16 accumulate

    const uint32_t arow = (uint32_t)(wm * 32 + (lid & 15));
    const uint32_t acs  = (uint32_t)((lid >> 4) * 16);        // A k-seg
    const uint32_t brow = (uint32_t)(wn * 32 + (lid & 7));
    const uint32_t bcs  = (uint32_t)(((lid >> 3) & 1) * 16);  // B k-seg
    const int q_ep = lid & 3, r_ep = lid >> 2;

    for (int j = 0; j < n_me; j++) {
        if ((j & 15) == 0) {
#pragma unroll
            for (int a = 0; a < 2; a++)
#pragma unroll
                for (int b = 0; b < 4; b++) {
#pragma unroll
                    for (int c = 0; c < 4; c++) acc[a][b][c] = 0.0f;
                    acc2[a][b][0] = 0u; acc2[a][b][1] = 0u;
                }
        }
        const uint32_t buf = (uint32_t)(j % NSTG);
        mbar_wait(sb + buf * 8, (uint32_t)((j / NSTG) & 1));   // full

        const uint32_t cb = sb + 1024 + buf * 32768;
        const uint32_t sAhi = cb, sAlo = cb + TIL;
        const uint32_t sBhi = cb + 2 * TIL, sBlo = cb + 3 * TIL;

#pragma unroll
        for (int k16 = 0; k16 < 2; k16++) {
            const uint32_t ax = (uint32_t)(k16 * 32) + acs;
            const uint32_t bx = (uint32_t)(k16 * 32) + bcs;
            uint32_t bhf[4][2], blf[4][2];
#pragma unroll
            for (int g = 0; g < 4; g++) {
                uint32_t ro = swz32(brow + (uint32_t)(g * 8), bx);
                ldsm2(bhf[g], sBhi + ro);
                ldsm2(blf[g], sBlo + ro);
            }
#pragma unroll
            for (int mt = 0; mt < 2; mt++) {
                uint32_t ro = swz32(arow + (uint32_t)(mt * 16), ax);
                uint32_t ah[4], al[4];
                ldsm4(ah, sAhi + ro);
                ldsm4(al, sAlo + ro);
#pragma unroll
                for (int g = 0; g < 4; g++) mma_f32(acc[mt][g], ah, bhf[g]);
#pragma unroll
                for (int g = 0; g < 4; g++) mma_f16(acc2[mt][g], ah, blf[g]);
#pragma unroll
                for (int g = 0; g < 4; g++) mma_f16(acc2[mt][g], al, bhf[g]);
            }
        }
        if (lid == 0) mbar_arrive(sb + 64 + buf * 8);  // this warp done
        if (tid == 0 && j + NSTG < n_me) issue_chunk(j + NSTG);

        if ((j & 15) == 15) {
            // ------------- fused LSTM epilogue for this tile -------------
            const int tile = o + (j >> 4) * grid;
            const int mx = tile >> 4, nx = tile & 15;
            const int m0 = mx * 128, n0 = nx * 128;
            const int cn0 = n0 + wn * 32;
            const int hcb = (cn0 >> 2) + 2 * q_ep;     // pair (hcb, hcb+1)
            const uint32_t ckh  = (uint32_t)(hcb >> 5);
            const uint32_t xoff = (uint32_t)((hcb & 31) * 2);

#pragma unroll
            for (int mt = 0; mt < 2; mt++) {
#pragma unroll
                for (int v = 0; v < 2; v++) {
                    const int ms = m0 + wm * 32 + mt * 16 + r_ep + v * 8;
                    const int L  = g_lens_s[ms];
                    const bool act = L > t;
                    const uint32_t tb  =
                        ((uint32_t)(ms >> 7) * NCK + ckh) * CK2;
                    const uint32_t off = swz32((uint32_t)(ms & 127), xoff);
                    __half2* phiO = (__half2*)(Aout + tb + off);
                    __half2* ploO = (__half2*)(Aout + tb + TIL + off);
                    if (act) {
                        const int orig = g_perm[ms];
                        const int id = seq[orig * SL + t];
                        const float* tr = g_tbl + id * G4 + cn0 + 2 * q_ep;
                        float2 cp = *(const float2*)(g_C + ms * HD + hcb);
                        float co[2] = {cp.x, cp.y};
                        float2 cr[4];
#pragma unroll
                        for (int g = 0; g < 4; g++)
                            cr[g] = __half22float2(
                                *(const __half2*)&acc2[mt][g][v]);
                        float h2[2], c2[2];
#pragma unroll
                        for (int jj = 0; jj < 2; jj++) {
                            float pi = acc[mt][0][2 * v + jj] +
                                       (jj ? cr[0].y : cr[0].x) + tr[0 + jj];
                            float pf = acc[mt][1][2 * v + jj] +
                                       (jj ? cr[1].y : cr[1].x) + tr[8 + jj];
                            float pg = acc[mt][2][2 * v + jj] +
                                       (jj ? cr[2].y : cr[2].x) + tr[16 + jj];
                            float po = acc[mt][3][2 * v + jj] +
                                       (jj ? cr[3].y : cr[3].x) + tr[24 + jj];
                            float ig = sigf(pi), fg = sigf(pf);
                            float gg = tanhfast(pg), og = sigf(po);
                            float cc = fg * co[jj] + ig * gg;
                            c2[jj] = cc;
                            h2[jj] = og * tanhfast(cc);
                        }
                        *(float2*)(g_C + ms * HD + hcb) =
                            make_float2(c2[0], c2[1]);
                        __half hi0 = __float2half_rn(h2[0]);
                        __half hi1 = __float2half_rn(h2[1]);
                        __half lo0 = __float2half_rn(h2[0] - __half2float(hi0));
                        __half lo1 = __float2half_rn(h2[1] - __half2float(hi1));
                        *phiO = __halves2half2(hi0, hi1);
                        *ploO = __halves2half2(lo0, lo1);
                        if (L == t + 1)                // freezes after this
                            *(float2*)(out_f + orig * HD + hcb) =
                                make_float2(h2[0], h2[1]);
                    } else {
                        // frozen boundary-tile row: forward for ping-pong
                        *phiO = *(const __half2*)(Ain + tb + off);
                        *ploO = *(const __half2*)(Ain + tb + TIL + off);
                    }
                }
            }
        }
    }
}

// ------------------------------ host entry --------------------------------
// Inputs: char_seq_padded(i32), char_lengths(i32), emb, W_ih, W_hh, b_ih, b_hh
extern "C" void kernel_launch(void* const* d_in, const int* in_sizes, int n_in,
                              void* d_out, int out_size) {
    const int*   seq  = (const int*)  d_in[0];
    const int*   lens = (const int*)  d_in[1];
    const float* emb  = (const float*)d_in[2];
    const float* W_ih = (const float*)d_in[3];
    const float* W_hh = (const float*)d_in[4];
    const float* b_ih = (const float*)d_in[5];
    const float* b_hh = (const float*)d_in[6];
    float* out = (float*)d_out;

    cudaFuncSetAttribute(lstm_step,
                         cudaFuncAttributeMaxDynamicSharedMemorySize,
                         SMEM_TOTAL);

    int dev = 0, smc = 148;
    cudaGetDevice(&dev);
    cudaDeviceGetAttribute(&smc, cudaDevAttrMultiProcessorCount, dev);

    prep_perm<<<1, 512>>>(lens);
    prep_w<<<(G4 * HD) / 256, 256>>>(W_hh);
    prep_tbl<<<dim3(G4 / 128, NV), 128>>>(emb, W_ih, b_ih, b_hh);
    step0<<<dim3(BT, HD / 128), 128>>>(seq, out);

    for (int t = 1; t < SL; t++)
        lstm_step<<<smc, 512, SMEM_TOTAL>>>(seq, out, t);
}

// round 17
// speedup vs baseline: 1.2961x; 1.0621x over previous
#include <cuda_runtime.h>
#include <cuda_fp16.h>
#include <cstdint>

// ===========================================================================
// CharLSTMEmbedding: B=32, T=128, L=16, VOCAB=256, E=256, H=512
// sm_103 plain target -> mma.sync HMMA + cp.async.bulk loads.
//
// R16: 2 CTAs/SM + mixed-precision accumulators + no spills, together:
//  * CTA tile 128m x 64n', 256 thr, 8 warps (4m x 2n), warp 32x32
//    -> 32 f32 + 16 f16 accs (~100 regs, fits 128-reg cap at occupancy 2)
//  * mixed accs: Ahi*Bhi -> f32 (rt 8); Ahi*Blo + Alo*Bhi -> f16 acc (rt 4)
//  * stage 24KB (A16 + B8), 4-stage pipeline, 97KB/CTA -> 2 CTAs/SM
//  * B ldsm4 covers 2 gates per load (8 ldsm/chunk/warp instead of 12)
//  * grid-stride continuous chunk pipeline, grid = 2 x #SM
//  * unchanged: sorted active prefix, fused epilogue, per-step launches.
// ===========================================================================

#define BT   4096
#define SL   16
#define HD   512
#define ED   256
#define NV   256
#define G4   2048

#define TILA 8192              // A: one 128x32-half tile (hi or lo)
#define CK2  16384             // A hi+lo pair
#define TILB 4096              // B: one 64x32-half tile (hi or lo)
#define CKB2 8192              // B hi+lo pair
#define NCK  16                // K chunks of 32
#define NSTG 4                 // pipeline stages
#define STGB 24576             // stage bytes: A pair + B pair

__device__ __align__(1024) unsigned char g_W[32 * NCK * CKB2];    // 4 MB
__device__ __align__(1024) unsigned char g_A[2][32 * NCK * CK2];  // 2 x 8 MB
__device__ __align__(256) float g_tbl[NV * G4];                   // 2 MB
__device__ __align__(256) float g_C[BT * HD];                     // 8 MB
__device__ int g_perm[BT];      // sorted-pos -> original row
__device__ int g_lens_s[BT];    // lens in sorted order (descending)
__device__ int g_Mt[SL];        // M_t = #(lens > t)

// ------------------------------ helpers -----------------------------------

__device__ __forceinline__ uint32_t smem_u32(const void* p) {
    uint32_t a;
    asm("{ .reg .u64 t; cvta.to.shared.u64 t, %1; cvt.u32.u64 %0, t; }"
        : "=r"(a) : "l"(p));
    return a;
}

// paired-row swizzle for (<=128)row x 64B tiles
__device__ __forceinline__ uint32_t swz32(uint32_t r, uint32_t x) {
    return (r >> 1) * 128u + ((((r & 1u) << 6) + x) ^ ((r & 14u) << 3));
}

__device__ __forceinline__ void bulk_cp(uint32_t dst, const void* src,
                                        uint32_t bytes, uint32_t mbar) {
    asm volatile(
        "cp.async.bulk.shared::cluster.global.mbarrier::complete_tx::bytes "
        "[%0], [%1], %2, [%3];"
        :: "r"(dst), "l"(src), "r"(bytes), "r"(mbar) : "memory");
}

__device__ __forceinline__ void mbar_init(uint32_t mbar, uint32_t cnt) {
    asm volatile("mbarrier.init.shared.b64 [%0], %1;" :: "r"(mbar), "r"(cnt)
                 : "memory");
}
__device__ __forceinline__ void mbar_expect(uint32_t mbar, uint32_t bytes) {
    asm volatile("mbarrier.arrive.expect_tx.shared.b64 _, [%0], %1;"
                 :: "r"(mbar), "r"(bytes) : "memory");
}
__device__ __forceinline__ void mbar_arrive(uint32_t mbar) {
    asm volatile("mbarrier.arrive.shared.b64 _, [%0];" :: "r"(mbar) : "memory");
}
__device__ __forceinline__ void mbar_wait(uint32_t mbar, uint32_t parity) {
    asm volatile(
        "{\n\t.reg .pred P;\n\t"
        "WL_%=:\n\t"
        "mbarrier.try_wait.parity.acquire.cta.shared::cta.b64 P, [%0], %1, 0x989680;\n\t"
        "@P bra.uni WD_%=;\n\t"
        "bra.uni WL_%=;\n\t"
        "WD_%=:\n\t}"
        :: "r"(mbar), "r"(parity) : "memory");
}

__device__ __forceinline__ void ldsm4(uint32_t* r, uint32_t addr) {
    asm volatile("ldmatrix.sync.aligned.m8n8.x4.shared.b16 {%0,%1,%2,%3}, [%4];"
                 : "=r"(r[0]), "=r"(r[1]), "=r"(r[2]), "=r"(r[3]) : "r"(addr));
}

// f32-accumulate HMMA (rt 8)
__device__ __forceinline__ void mma_f32(float* d, const uint32_t* a,
                                        const uint32_t* b) {
    asm volatile(
        "mma.sync.aligned.m16n8k16.row.col.f32.f16.f16.f32 "
        "{%0,%1,%2,%3}, {%4,%5,%6,%7}, {%8,%9}, {%0,%1,%2,%3};"
        : "+f"(d[0]), "+f"(d[1]), "+f"(d[2]), "+f"(d[3])
        : "r"(a[0]), "r"(a[1]), "r"(a[2]), "r"(a[3]), "r"(b[0]), "r"(b[1]));
}
// f16-accumulate HMMA (rt 4) for the small correction terms
__device__ __forceinline__ void mma_f16(uint32_t* d, const uint32_t* a,
                                        const uint32_t* b) {
    asm volatile(
        "mma.sync.aligned.m16n8k16.row.col.f16.f16.f16.f16 "
        "{%0,%1}, {%2,%3,%4,%5}, {%6,%7}, {%0,%1};"
        : "+r"(d[0]), "+r"(d[1])
        : "r"(a[0]), "r"(a[1]), "r"(a[2]), "r"(a[3]), "r"(b[0]), "r"(b[1]));
}

__device__ __forceinline__ float sigf(float x) {
    return __fdividef(1.0f, 1.0f + __expf(-x));
}
__device__ __forceinline__ float tanhfast(float x) {
    return __fdividef(2.0f, 1.0f + __expf(-2.0f * x)) - 1.0f;
}

// ------------------------------ prep kernels ------------------------------

// counting sort by length, descending; deterministic within-bin order.
__global__ void prep_perm(const int* __restrict__ lens) {
    __shared__ int cnt[17], off[17];
    int tid = threadIdx.x;
    if (tid < 17) cnt[tid] = 0;
    __syncthreads();
    for (int i = tid; i < BT; i += 512) atomicAdd(&cnt[lens[i]], 1);
    __syncthreads();
    if (tid == 0) {
        int acc = 0;
        for (int l = 16; l >= 1; l--) { off[l] = acc; acc += cnt[l]; }
        g_Mt[0] = BT;
        for (int t = 1; t < SL; t++) g_Mt[t] = off[t];   // #(lens > t)
    }
    __syncthreads();
    int w = tid >> 5, lane = tid & 31;
    int l = w + 1;                                   // bins 1..16
    int p = off[l];
    for (int base = 0; base < BT; base += 32) {
        int i = base + lane;
        bool m = (lens[i] == l);
        unsigned msk = __ballot_sync(0xffffffffu, m);
        if (m) {
            int rank = __popc(msk & ((1u << lane) - 1));
            g_perm[p + rank] = i;
            g_lens_s[p + rank] = l;
        }
        p += __popc(msk);
    }
}

// W packed as [nx64(32)][ck(16)][hi 4KB | lo 4KB], 64-row tiles
__global__ void prep_w(const float* __restrict__ W) {
    int idx = blockIdx.x * 256 + threadIdx.x;      // < G4*HD
    int np = idx >> 9, k = idx & 511;
    int hc = ((np >> 5) << 3) + (np & 7);
    int g  = (np >> 3) & 3;
    float v = W[(g * HD + hc) * HD + k];
    __half hi = __float2half_rn(v);
    __half lo = __float2half_rn(v - __half2float(hi));
    uint32_t base = (uint32_t)((np >> 6) * NCK + (k >> 5)) * CKB2;
    uint32_t off  = swz32((uint32_t)(np & 63), (uint32_t)((k & 31) * 2));
    *(__half*)(g_W + base + off)        = hi;
    *(__half*)(g_W + base + TILB + off) = lo;
}

__global__ void prep_tbl(const float* __restrict__ emb,
                         const float* __restrict__ Wih,
                         const float* __restrict__ bi,
                         const float* __restrict__ bh) {
    __shared__ __align__(16) float e[ED];
    int v = blockIdx.y;
    for (int i = threadIdx.x; i < ED; i += blockDim.x)
        e[i] = emb[v * ED + i];
    __syncthreads();

    int np = blockIdx.x * 128 + threadIdx.x;
    int hc = ((np >> 5) << 3) + (np & 7);
    int g  = (np >> 3) & 3;
    int n  = g * HD + hc;
    const float4* w4 = (const float4*)(Wih + n * ED);
    const float4* e4 = (const float4*)e;
    float s = bi[n] + bh[n];
#pragma unroll 8
    for (int k = 0; k < ED / 4; k++) {
        float4 wv = w4[k];
        float4 ev = e4[k];
        s += ev.x * wv.x + ev.y * wv.y + ev.z * wv.z + ev.w * wv.w;
    }
    g_tbl[v * G4 + np] = s;
}

// step 0 in sorted row space; rows with lens==1 freeze here -> write out
__global__ void step0(const int* __restrict__ seq, float* __restrict__ out) {
    int ms = blockIdx.x;                       // sorted row
    int hc = blockIdx.y * 128 + threadIdx.x;
    int orig = g_perm[ms];
    int id = seq[orig * SL];
    int base = ((hc >> 3) << 5) + (hc & 7);    // gate stride 8 in tbl
    const float* tr = g_tbl + id * G4;
    float cn = sigf(tr[base]) * tanhfast(tr[base + 16]);
    float hn = sigf(tr[base + 24]) * tanhfast(cn);
    __half hi = __float2half_rn(hn);
    __half lo = __float2half_rn(hn - __half2float(hi));
    uint32_t tb  = (uint32_t)((ms >> 7) * NCK + (hc >> 5)) * CK2;
    uint32_t off = swz32((uint32_t)(ms & 127), (uint32_t)((hc & 31) * 2));
    *(__half*)(g_A[0] + tb + off)        = hi;
    *(__half*)(g_A[0] + tb + TILA + off) = lo;
    g_C[ms * HD + hc] = cn;
    if (g_lens_s[ms] == 1) out[orig * HD + hc] = hn;
}

// --------------------------- recurrent step -------------------------------
// grid = 2 * #SMs, 256 threads, 8 warps (4m x 2n), warp 32x32, 2 CTAs/SM.
// Grid-stride over 128x64 tiles; continuous 4-stage chunk pipeline.

#define SMEM_TOTAL (1024 + NSTG * STGB)

__global__ void __launch_bounds__(256, 2)
lstm_step(const int* __restrict__ seq, float* __restrict__ out_f, int t) {
    const int Mpad = (g_Mt[t] + 127) & ~127;
    const int ntiles = (Mpad >> 7) * 32;           // 128x64 tiles
    const int o = (int)blockIdx.x;
    const int grid = (int)gridDim.x;
    const int mytiles = (o < ntiles) ? ((ntiles - 1 - o) / grid + 1) : 0;
    const int n_me = mytiles << 4;
    if (n_me == 0) return;

    extern __shared__ char smem[];
    const uint32_t sb = smem_u32(smem);
    const int tid = threadIdx.x, lid = tid & 31;
    const int wm = (tid >> 5) >> 1;            // 0..3 (m group)
    const int wn = (tid >> 5) & 1;             // 0..1 (n group)

    const unsigned char* __restrict__ Abase = g_A[(t + 1) & 1];
    unsigned char* __restrict__ Aout = g_A[t & 1];
    const unsigned char* __restrict__ Ain = Abase;

    // mbars: full[b] @ sb+b*8 (count1, tx), empty[b] @ sb+64+b*8 (count 8)
    if (tid == 0) {
#pragma unroll
        for (int b = 0; b < NSTG; b++) {
            mbar_init(sb + b * 8, 1);
            mbar_init(sb + 64 + b * 8, 8);
        }
    }
    __syncthreads();

    auto issue_chunk = [&](int j) {
        const int tile = o + (j >> 4) * grid;
        const int mx = tile >> 5, nx = tile & 31, ck = j & 15;
        const int u = j / NSTG;
        const uint32_t buf = (uint32_t)(j % NSTG);
        if (u > 0) mbar_wait(sb + 64 + buf * 8, (uint32_t)((u - 1) & 1));
        const uint32_t dst = sb + 1024 + buf * STGB;
        const uint32_t mb  = sb + buf * 8;
        mbar_expect(mb, STGB);
        bulk_cp(dst,         Abase + ((size_t)mx * NCK + ck) * CK2,  CK2,  mb);
        bulk_cp(dst + CK2,   g_W   + ((size_t)nx * NCK + ck) * CKB2, CKB2, mb);
    };
    if (tid == 0) {
        const int pre = n_me < NSTG ? n_me : NSTG;
        for (int jj = 0; jj < pre; jj++) issue_chunk(jj);
    }

    float    acc [2][4][4];          // main term, f32 accumulate
    uint32_t acc2[2][4][2];          // corrections, f16 accumulate

    const uint32_t arow = (uint32_t)(wm * 32 + (lid & 15));
    const uint32_t acs  = (uint32_t)((lid >> 4) * 16);        // A k-seg
    // B ldsm4 (2 gates / load): row + k-seg per lane
    const uint32_t brow = (uint32_t)(wn * 32 + ((lid >> 4) & 1) * 8 + (lid & 7));
    const uint32_t bcs  = (uint32_t)(((lid >> 3) & 1) * 16);  // B k-seg
    const int q_ep = lid & 3, r_ep = lid >> 2;

    for (int j = 0; j < n_me; j++) {
        if ((j & 15) == 0) {
#pragma unroll
            for (int a = 0; a < 2; a++)
#pragma unroll
                for (int b = 0; b < 4; b++) {
#pragma unroll
                    for (int c = 0; c < 4; c++) acc[a][b][c] = 0.0f;
                    acc2[a][b][0] = 0u; acc2[a][b][1] = 0u;
                }
        }
        const uint32_t buf = (uint32_t)(j % NSTG);
        mbar_wait(sb + buf * 8, (uint32_t)((j / NSTG) & 1));   // full

        const uint32_t cb = sb + 1024 + buf * STGB;
        const uint32_t sAhi = cb, sAlo = cb + TILA;
        const uint32_t sBhi = cb + CK2, sBlo = cb + CK2 + TILB;

#pragma unroll
        for (int k16 = 0; k16 < 2; k16++) {
            const uint32_t ax = (uint32_t)(k16 * 32) + acs;
            const uint32_t bx = (uint32_t)(k16 * 32) + bcs;
            // B fragments: one ldsm4 = 2 gates (per precision, per pair)
            uint32_t bhf[4][2], blf[4][2];
#pragma unroll
            for (int gp = 0; gp < 2; gp++) {
                uint32_t ro = swz32(brow + (uint32_t)(gp * 16), bx);
                ldsm4(&bhf[gp * 2][0], sBhi + ro);   // {g,k0},{g,k1},{g+1,k0},{g+1,k1}
                ldsm4(&blf[gp * 2][0], sBlo + ro);
            }
#pragma unroll
            for (int mt = 0; mt < 2; mt++) {
                uint32_t ro = swz32(arow + (uint32_t)(mt * 16), ax);
                uint32_t ah[4], al[4];
                ldsm4(ah, sAhi + ro);
                ldsm4(al, sAlo + ro);
#pragma unroll
                for (int g = 0; g < 4; g++) mma_f32(acc[mt][g], ah, bhf[g]);
#pragma unroll
                for (int g = 0; g < 4; g++) mma_f16(acc2[mt][g], ah, blf[g]);
#pragma unroll
                for (int g = 0; g < 4; g++) mma_f16(acc2[mt][g], al, bhf[g]);
            }
        }
        if (lid == 0) mbar_arrive(sb + 64 + buf * 8);  // this warp done
        if (tid == 0 && j + NSTG < n_me) issue_chunk(j + NSTG);

        if ((j & 15) == 15) {
            // ------------- fused LSTM epilogue for this tile -------------
            const int tile = o + (j >> 4) * grid;
            const int mx = tile >> 5, nx = tile & 31;
            const int m0 = mx * 128, n0 = nx * 64;
            const int cn0 = n0 + wn * 32;
            const int hcb = (cn0 >> 2) + 2 * q_ep;     // pair (hcb, hcb+1)
            const uint32_t ckh  = (uint32_t)(hcb >> 5);
            const uint32_t xoff = (uint32_t)((hcb & 31) * 2);

#pragma unroll
            for (int mt = 0; mt < 2; mt++) {
#pragma unroll
                for (int v = 0; v < 2; v++) {
                    const int ms = m0 + wm * 32 + mt * 16 + r_ep + v * 8;
                    const int L  = g_lens_s[ms];
                    const bool act = L > t;
                    const uint32_t tb  =
                        ((uint32_t)(ms >> 7) * NCK + ckh) * CK2;
                    const uint32_t off = swz32((uint32_t)(ms & 127), xoff);
                    __half2* phiO = (__half2*)(Aout + tb + off);
                    __half2* ploO = (__half2*)(Aout + tb + TILA + off);
                    if (act) {
                        const int orig = g_perm[ms];
                        const int id = seq[orig * SL + t];
                        const float* tr = g_tbl + id * G4 + cn0 + 2 * q_ep;
                        float2 cp = *(const float2*)(g_C + ms * HD + hcb);
                        float co[2] = {cp.x, cp.y};
                        float2 cr[4];
#pragma unroll
                        for (int g = 0; g < 4; g++)
                            cr[g] = __half22float2(
                                *(const __half2*)&acc2[mt][g][v]);
                        float h2[2], c2[2];
#pragma unroll
                        for (int jj = 0; jj < 2; jj++) {
                            float pi = acc[mt][0][2 * v + jj] +
                                       (jj ? cr[0].y : cr[0].x) + tr[0 + jj];
                            float pf = acc[mt][1][2 * v + jj] +
                                       (jj ? cr[1].y : cr[1].x) + tr[8 + jj];
                            float pg = acc[mt][2][2 * v + jj] +
                                       (jj ? cr[2].y : cr[2].x) + tr[16 + jj];
                            float po = acc[mt][3][2 * v + jj] +
                                       (jj ? cr[3].y : cr[3].x) + tr[24 + jj];
                            float ig = sigf(pi), fg = sigf(pf);
                            float gg = tanhfast(pg), og = sigf(po);
                            float cc = fg * co[jj] + ig * gg;
                            c2[jj] = cc;
                            h2[jj] = og * tanhfast(cc);
                        }
                        *(float2*)(g_C + ms * HD + hcb) =
                            make_float2(c2[0], c2[1]);
                        __half hi0 = __float2half_rn(h2[0]);
                        __half hi1 = __float2half_rn(h2[1]);
                        __half lo0 = __float2half_rn(h2[0] - __half2float(hi0));
                        __half lo1 = __float2half_rn(h2[1] - __half2float(hi1));
                        *phiO = __halves2half2(hi0, hi1);
                        *ploO = __halves2half2(lo0, lo1);
                        if (L == t + 1)                // freezes after this
                            *(float2*)(out_f + orig * HD + hcb) =
                                make_float2(h2[0], h2[1]);
                    } else {
                        // frozen boundary-tile row: forward for ping-pong
                        *phiO = *(const __half2*)(Ain + tb + off);
                        *ploO = *(const __half2*)(Ain + tb + TILA + off);
                    }
                }
            }
        }
    }
}

// ------------------------------ host entry --------------------------------
// Inputs: char_seq_padded(i32), char_lengths(i32), emb, W_ih, W_hh, b_ih, b_hh
extern "C" void kernel_launch(void* const* d_in, const int* in_sizes, int n_in,
                              void* d_out, int out_size) {
    const int*   seq  = (const int*)  d_in[0];
    const int*   lens = (const int*)  d_in[1];
    const float* emb  = (const float*)d_in[2];
    const float* W_ih = (const float*)d_in[3];
    const float* W_hh = (const float*)d_in[4];
    const float* b_ih = (const float*)d_in[5];
    const float* b_hh = (const float*)d_in[6];
    float* out = (float*)d_out;

    cudaFuncSetAttribute(lstm_step,
                         cudaFuncAttributeMaxDynamicSharedMemorySize,
                         SMEM_TOTAL);

    int dev = 0, smc = 148;
    cudaGetDevice(&dev);
    cudaDeviceGetAttribute(&smc, cudaDevAttrMultiProcessorCount, dev);

    prep_perm<<<1, 512>>>(lens);
    prep_w<<<(G4 * HD) / 256, 256>>>(W_hh);
    prep_tbl<<<dim3(G4 / 128, NV), 128>>>(emb, W_ih, b_ih, b_hh);
    step0<<<dim3(BT, HD / 128), 128>>>(seq, out);

    for (int t = 1; t < SL; t++)
        lstm_step<<<smc * 2, 256, SMEM_TOTAL>>>(seq, out, t);
}